// round 16
// baseline (speedup 1.0000x reference)
#include <cuda_runtime.h>
#include <math.h>
#include <stdint.h>

// ---------------- problem constants ----------------
#define BSZ 2
#define CH  64
#define NPT 400
#define LT  12
#define DM  128
#define NH  8
#define HDM 16
#define FFD 1024

#define NTOK (BSZ*LT*NPT)          // 9600 tokens (b,l,n)
#define NROW (BSZ*NH*LT*NPT)       // 76800 attention rows (b,h,l,n)
#define OUT0 (BSZ*CH*NPT*LT)       // 614400

#define EPS_LN 1e-5f
#define NEG_INF (__int_as_float(0xff800000))

// ---------------- f32x2 packed helpers ----------------
__device__ __forceinline__ unsigned long long fma2(
    unsigned long long a, unsigned long long b, unsigned long long c) {
    unsigned long long d;
    asm("fma.rn.f32x2 %0, %1, %2, %3;" : "=l"(d) : "l"(a), "l"(b), "l"(c));
    return d;
}
__device__ __forceinline__ unsigned long long pack2(float lo, float hi) {
    unsigned long long d;
    asm("mov.b64 %0, {%1, %2};" : "=l"(d) : "f"(lo), "f"(hi));
    return d;
}
__device__ __forceinline__ void unpack2(unsigned long long v, float& lo, float& hi) {
    asm("mov.b64 {%0, %1}, %2;" : "=f"(lo), "=f"(hi) : "l"(v));
}

// ---------------- scratch (device globals, no allocation) ----------------
__device__ float g_q1[NTOK*DM];
__device__ float g_q2[NTOK*DM];
__device__ float g_k1[NTOK*DM];
__device__ float g_k2[NTOK*DM];
__device__ float g_v [NTOK*DM];
__device__ float g_aout [NTOK*DM];     // m-half 0 partial
__device__ float g_aout2[NTOK*DM];     // m-half 1 partial
__device__ float g_w [(size_t)NROW*NPT];   // combined attention weights (123MB)

// =====================================================================
// Kernel 1: projections + per-head l2 norm. 4 tokens per block,
// token-pairs packed f32x2; weight LDG amortized 4x.  (R12-verified)
// =====================================================================
__global__ __launch_bounds__(160) void k1_proj(
    const float* __restrict__ x, const float* __restrict__ xa1, const float* __restrict__ xa2,
    const float* __restrict__ WQ1, const float* __restrict__ bQ1,
    const float* __restrict__ WQ2, const float* __restrict__ bQ2,
    const float* __restrict__ WK1, const float* __restrict__ bK1,
    const float* __restrict__ WK2, const float* __restrict__ bK2,
    const float* __restrict__ WV,  const float* __restrict__ bV)
{
    int t0 = blockIdx.x * 4;
    __shared__ __align__(16) float s_in[3*CH*4];   // [arr*64+c][t], stride 4
    int tid = threadIdx.x;
    for (int idx = tid; idx < 3*CH*4; idx += 160) {
        int ci = idx >> 2, t = idx & 3;
        int arr = ci >> 6, c = ci & 63;
        const float* src = (arr == 0) ? x : (arr == 1 ? xa1 : xa2);
        int tt = t0 + t;
        int b = tt / (LT*NPT); int rem = tt % (LT*NPT);
        int l = rem / NPT;     int n = rem % NPT;
        s_in[ci*4 + t] = src[((size_t)(b*CH + c)*NPT + n)*LT + l];
    }
    __syncthreads();

    int p = tid >> 5, dg = tid & 31;       // p uniform per warp
    const float* W    = (p==0)?WQ1 : (p==1)?WQ2 : (p==2)?WK1 : (p==3)?WK2 : WV;
    const float* bias = (p==0)?bQ1 : (p==1)?bQ2 : (p==2)?bK1 : (p==3)?bK2 : bV;
    int soff = (p==0) ? CH : (p==1 ? 2*CH : 0);   // xa1 / xa2 / x

    float4 bb = *(const float4*)&bias[4*dg];
    unsigned long long acc2[2][4];
    {
        unsigned long long b0 = pack2(bb.x, bb.x), b1 = pack2(bb.y, bb.y);
        unsigned long long b2 = pack2(bb.z, bb.z), b3 = pack2(bb.w, bb.w);
        acc2[0][0] = b0; acc2[0][1] = b1; acc2[0][2] = b2; acc2[0][3] = b3;
        acc2[1][0] = b0; acc2[1][1] = b1; acc2[1][2] = b2; acc2[1][3] = b3;
    }
    #pragma unroll 4
    for (int c = 0; c < CH; c++) {
        float4 w = *(const float4*)&W[c*DM + 4*dg];
        unsigned long long w0 = pack2(w.x, w.x), w1 = pack2(w.y, w.y);
        unsigned long long w2 = pack2(w.z, w.z), w3 = pack2(w.w, w.w);
        unsigned long long rv0 = *(const unsigned long long*)&s_in[(soff + c)*4];
        unsigned long long rv1 = *(const unsigned long long*)&s_in[(soff + c)*4 + 2];
        acc2[0][0] = fma2(rv0, w0, acc2[0][0]);
        acc2[0][1] = fma2(rv0, w1, acc2[0][1]);
        acc2[0][2] = fma2(rv0, w2, acc2[0][2]);
        acc2[0][3] = fma2(rv0, w3, acc2[0][3]);
        acc2[1][0] = fma2(rv1, w0, acc2[1][0]);
        acc2[1][1] = fma2(rv1, w1, acc2[1][1]);
        acc2[1][2] = fma2(rv1, w2, acc2[1][2]);
        acc2[1][3] = fma2(rv1, w3, acc2[1][3]);
    }
    // unpack to per-token values v[t][j]
    float v[4][4];
    #pragma unroll
    for (int pp = 0; pp < 2; pp++)
        #pragma unroll
        for (int j = 0; j < 4; j++)
            unpack2(acc2[pp][j], v[2*pp][j], v[2*pp + 1][j]);

    float* dst = (p==0)?g_q1 : (p==1)?g_q2 : (p==2)?g_k1 : (p==3)?g_k2 : g_v;
    #pragma unroll
    for (int t = 0; t < 4; t++) {
        float a0 = v[t][0], a1 = v[t][1], a2 = v[t][2], a3 = v[t][3];
        if (p < 4) {  // l2norm per head (head = 16 dims = 4 consecutive lanes)
            float ss = a0*a0 + a1*a1 + a2*a2 + a3*a3;
            ss += __shfl_xor_sync(0xffffffffu, ss, 1);
            ss += __shfl_xor_sync(0xffffffffu, ss, 2);
            float inv = 1.0f / fmaxf(sqrtf(ss), 1e-12f);
            a0 *= inv; a1 *= inv; a2 *= inv; a3 *= inv;
        }
        *(float4*)&dst[(size_t)(t0 + t)*DM + 4*dg] = make_float4(a0, a1, a2, a3);
    }
}

// =====================================================================
// Kernel 2: attn = temp*(q1.k1 + q2.k2) via f32x2 packed pairs.
// STRIDED m-assignment: conflict-free LDS.64.  (R13-verified)
// =====================================================================
__global__ __launch_bounds__(256) void k2_attn(
    float* __restrict__ attn, const float* __restrict__ temperature)
{
    int tile = blockIdx.x;
    int nb = tile / 7, mb = tile % 7;
    int bhl = blockIdx.y;
    int b = bhl / (NH*LT); int h = (bhl / LT) % NH; int l = bhl % LT;
    int baset = (b*LT + l)*NPT;

    __shared__ __align__(16) unsigned long long Qs2[64*17];  // [n][d] pairs
    __shared__ __align__(16) unsigned long long Ks2[64*17];  // [m][d] pairs
    int tid = threadIdx.x;

    {
        int row = tid >> 2, qq = tid & 3;
        int n = nb*64 + row;
        float4 a = make_float4(0,0,0,0), bq = a;
        if (n < NPT) {
            size_t base = (size_t)(baset + n)*DM + h*HDM;
            a  = *(const float4*)&g_q1[base + qq*4];
            bq = *(const float4*)&g_q2[base + qq*4];
        }
        unsigned long long* dstq = &Qs2[row*17 + qq*4];
        dstq[0] = pack2(a.x, bq.x); dstq[1] = pack2(a.y, bq.y);
        dstq[2] = pack2(a.z, bq.z); dstq[3] = pack2(a.w, bq.w);
        int m = mb*64 + row;
        a = make_float4(0,0,0,0); bq = a;
        if (m < NPT) {
            size_t base = (size_t)(baset + m)*DM + h*HDM;
            a  = *(const float4*)&g_k1[base + qq*4];
            bq = *(const float4*)&g_k2[base + qq*4];
        }
        unsigned long long* dstk = &Ks2[row*17 + qq*4];
        dstk[0] = pack2(a.x, bq.x); dstk[1] = pack2(a.y, bq.y);
        dstk[2] = pack2(a.z, bq.z); dstk[3] = pack2(a.w, bq.w);
    }
    __syncthreads();

    int tx = tid & 15, ty = tid >> 4;     // n = ty + 16i, m = tx + 16j
    unsigned long long acc2[4][4];
    {
        unsigned long long z = pack2(0.f, 0.f);
        #pragma unroll
        for (int i = 0; i < 4; i++)
            #pragma unroll
            for (int j = 0; j < 4; j++) acc2[i][j] = z;
    }
    #pragma unroll
    for (int kk = 0; kk < 16; kk++) {
        unsigned long long qr[4], kr[4];
        #pragma unroll
        for (int i = 0; i < 4; i++) qr[i] = Qs2[(ty + 16*i)*17 + kk];
        #pragma unroll
        for (int j = 0; j < 4; j++) kr[j] = Ks2[(tx + 16*j)*17 + kk];
        #pragma unroll
        for (int i = 0; i < 4; i++)
            #pragma unroll
            for (int j = 0; j < 4; j++)
                acc2[i][j] = fma2(qr[i], kr[j], acc2[i][j]);
    }

    float temp = temperature[h];
    size_t base = (size_t)bhl * NPT * NPT;
    #pragma unroll
    for (int i = 0; i < 4; i++) {
        int n = nb*64 + ty + 16*i;
        if (n >= NPT) continue;
        #pragma unroll
        for (int j = 0; j < 4; j++) {
            int m = mb*64 + tx + 16*j;
            if (m < NPT) {
                float lo, hi; unpack2(acc2[i][j], lo, hi);
                attn[base + (size_t)n*NPT + m] = (lo + hi)*temp;
            }
        }
    }
}

// =====================================================================
// Kernel 3: warp-per-row EXACT select (1 shared histogram, plain
// atomics), softmax, writes p2_flat + g_w.  (R13/R15-verified)
// =====================================================================
__device__ __forceinline__ void walk_bins(
    const unsigned int c[8], unsigned int k, int lane,
    unsigned int& bsel, unsigned int& krem)
{
    unsigned int lsum = 0;
    #pragma unroll
    for (int b = 0; b < 8; b++) lsum += c[b];
    unsigned int s = lsum;                       // suffix sum over lanes >= lane
    #pragma unroll
    for (int o = 1; o < 32; o <<= 1) {
        unsigned int t = __shfl_down_sync(0xffffffffu, s, o);
        if (lane + o < 32) s += t;
    }
    unsigned int excl = __shfl_down_sync(0xffffffffu, s, 1);
    if (lane == 31) excl = 0u;
    unsigned int ball = __ballot_sync(0xffffffffu, (excl < k) && (excl + lsum >= k));
    int src = __ffs((int)ball) - 1;
    unsigned int dig = 0, nk = 0;
    if (lane == src) {
        unsigned int cum = excl, cumsel = excl;
        int bs = 0; bool fnd = false;
        #pragma unroll
        for (int b = 7; b >= 0; b--) {
            if (!fnd && (cum + c[b] >= k)) { bs = b; cumsel = cum; fnd = true; }
            if (!fnd) cum += c[b];
        }
        dig = (unsigned)(lane*8 + bs);
        nk  = k - cumsel;
    }
    bsel = __shfl_sync(0xffffffffu, dig, src);
    krem = __shfl_sync(0xffffffffu, nk,  src);
}

__device__ __forceinline__ unsigned int select_kth(
    const unsigned int u[13], int lane, unsigned int* hist,
    unsigned int lo, int shift, const unsigned int c0[8], unsigned int k)
{
    unsigned int bsel, krem;
    walk_bins(c0, k, lane, bsel, krem);
    lo += bsel << shift;
    k = krem;
    while (shift > 0) {                      // warp-uniform
        int ns = (shift > 8) ? shift - 8 : 0;
        unsigned int hi2 = lo + ((1u << shift) - 1u);
        #pragma unroll
        for (int b = 0; b < 8; b++) hist[lane*8 + b] = 0u;
        __syncwarp();
        #pragma unroll
        for (int i = 0; i < 13; i++) {
            unsigned int key = u[i];
            if (key >= lo && key <= hi2)
                atomicAdd(&hist[(key - lo) >> ns], 1u);
        }
        __syncwarp();
        unsigned int c[8];
        #pragma unroll
        for (int b = 0; b < 8; b++) c[b] = hist[lane*8 + b];
        __syncwarp();
        walk_bins(c, k, lane, bsel, krem);
        lo += bsel << ns;
        k = krem;
        shift = ns;
    }
    return lo;   // exact key of k-th largest
}

__global__ __launch_bounds__(256) void k3_topk(
    const float* __restrict__ attn, float* __restrict__ p2out,
    const float* __restrict__ alphas)
{
    __shared__ unsigned int hist_all[8*256];
    int wib = threadIdx.x >> 5, lane = threadIdx.x & 31;
    unsigned int* hist = &hist_all[wib*256];
    int r = blockIdx.x*8 + wib;

    const float* row = attn + (size_t)r*NPT;
    float f[13]; unsigned int u[13];
    #pragma unroll
    for (int i = 0; i < 13; i++) {
        int m = lane + 32*i;
        float v = (m < NPT) ? row[m] : NEG_INF;
        f[i] = v;
        unsigned int bb = __float_as_uint(v);
        unsigned int key = (bb & 0x80000000u) ? ~bb : (bb | 0x80000000u);
        u[i] = (m < NPT) ? key : 0u;        // pads: key 0, excluded everywhere
    }
    float mx = NEG_INF;
    unsigned int lo = 0xFFFFFFFFu, hi = 0u;
    #pragma unroll
    for (int i = 0; i < 13; i++) {
        int m = lane + 32*i;
        if (m < NPT) {
            mx = fmaxf(mx, f[i]);
            lo = min(lo, u[i]);
            hi = max(hi, u[i]);
        }
    }
    #pragma unroll
    for (int o = 16; o; o >>= 1) {
        mx = fmaxf(mx, __shfl_xor_sync(0xffffffffu, mx, o));
        lo = min(lo, __shfl_xor_sync(0xffffffffu, lo, o));
        hi = max(hi, __shfl_xor_sync(0xffffffffu, hi, o));
    }
    unsigned int range = hi - lo;
    int rb = (range == 0u) ? 0 : (32 - __clz(range));
    int shift = (rb > 8) ? rb - 8 : 0;

    // single full histogram pass (plain atomics; shared by both selects)
    #pragma unroll
    for (int bq = 0; bq < 8; bq++) hist[lane*8 + bq] = 0u;
    __syncwarp();
    #pragma unroll
    for (int i = 0; i < 13; i++) {
        int m = lane + 32*i;
        if (m < NPT) atomicAdd(&hist[(u[i] - lo) >> shift], 1u);
    }
    __syncwarp();
    unsigned int c0[8];
    #pragma unroll
    for (int bq = 0; bq < 8; bq++) c0[bq] = hist[lane*8 + bq];
    __syncwarp();

    unsigned int t1u = select_kth(u, lane, hist, lo, shift, c0, 200u);
    unsigned int t2u = select_kth(u, lane, hist, lo, shift, c0, 100u);

    float l1 = 0.f, l2 = 0.f;
    #pragma unroll
    for (int i = 0; i < 13; i++) {
        float e = __expf(f[i] - mx);        // pads: exp(-inf)=0
        f[i] = e;
        if (u[i] >= t1u) { l1 += e; if (u[i] >= t2u) l2 += e; }
    }
    #pragma unroll
    for (int o = 16; o; o >>= 1) {
        l1 += __shfl_xor_sync(0xffffffffu, l1, o);
        l2 += __shfl_xor_sync(0xffffffffu, l2, o);
    }
    float i1 = 1.0f/l1, i2 = 1.0f/l2;

    float a0 = alphas[0], a1 = alphas[1];
    float am = fmaxf(a0, a1);
    float e0 = __expf(a0 - am), e1 = __expf(a1 - am);
    float al0 = e0/(e0 + e1), al1 = e1/(e0 + e1);

    float* prow = p2out + (size_t)r*NPT;
    float* wrow = g_w   + (size_t)r*NPT;
    #pragma unroll
    for (int i = 0; i < 13; i++) {
        int m = lane + 32*i;
        if (m < NPT) {
            float e  = f[i];
            float p1 = (u[i] >= t1u) ? e*i1 : 0.f;
            float p2 = (u[i] >= t2u) ? e*i2 : 0.f;
            prow[m] = p2;
            wrow[m] = al0*p1 + al1*p2;
        }
    }
}

// =====================================================================
// Kernel 4: aout = W @ V per (b,h,l), SPLIT-M: blockIdx.x encodes
// (row-block 0..1, m-half 0..1). Partials to g_aout / g_aout2 (k5 sums).
// 200-row blocks, 4 rows/thread, 40-col chunks. grid 4x192 -> occ ~64%.
// =====================================================================
__global__ __launch_bounds__(256) void k4_av()
{
    int nb  = blockIdx.x & 1;        // row-block: 200 rows each
    int mh  = blockIdx.x >> 1;       // m-half: [0,200) or [200,400)
    int bhl = blockIdx.y;
    int b = bhl / (NH*LT); int h = (bhl / LT) % NH; int l = bhl % LT;
    int blN = (b*LT + l)*NPT;

    __shared__ __align__(16) float Wsh[200*44];   // 35.2KB
    __shared__ __align__(16) float Vsh[40*16];    // 2.56KB

    int tid = threadIdx.x;
    int vg = tid & 3, rt = tid >> 2;              // rt 0..63

    size_t wbase = ((size_t)bhl*NPT + nb*200)*NPT;
    int m0 = mh*200;

    float4 acc[4];
    #pragma unroll
    for (int i = 0; i < 4; i++) acc[i] = make_float4(0.f, 0.f, 0.f, 0.f);

    for (int mc = m0; mc < m0 + 200; mc += 40) {
        __syncthreads();
        for (int idx = tid; idx < 200*10; idx += 256) {
            int rr = idx/10, cc = idx%10;
            *(float4*)&Wsh[rr*44 + cc*4] =
                *(const float4*)&g_w[wbase + (size_t)rr*NPT + mc + cc*4];
        }
        for (int idx = tid; idx < 40*4; idx += 256) {
            int rr = idx >> 2, c4 = idx & 3;
            *(float4*)&Vsh[rr*16 + c4*4] =
                *(const float4*)&g_v[(size_t)(blN + mc + rr)*DM + h*HDM + c4*4];
        }
        __syncthreads();
        #pragma unroll 2
        for (int ml = 0; ml < 40; ml += 4) {
            float4 v0 = *(const float4*)&Vsh[(ml+0)*16 + vg*4];
            float4 v1 = *(const float4*)&Vsh[(ml+1)*16 + vg*4];
            float4 v2 = *(const float4*)&Vsh[(ml+2)*16 + vg*4];
            float4 v3 = *(const float4*)&Vsh[(ml+3)*16 + vg*4];
            #pragma unroll
            for (int i = 0; i < 4; i++) {
                if (i == 3 && rt >= 8) break;        // rows 192..199 only
                float4 w = *(const float4*)&Wsh[(rt + 64*i)*44 + ml];
                acc[i].x += w.x*v0.x + w.y*v1.x + w.z*v2.x + w.w*v3.x;
                acc[i].y += w.x*v0.y + w.y*v1.y + w.z*v2.y + w.w*v3.y;
                acc[i].z += w.x*v0.z + w.y*v1.z + w.z*v2.z + w.w*v3.z;
                acc[i].w += w.x*v0.w + w.y*v1.w + w.z*v2.w + w.w*v3.w;
            }
        }
    }
    float* dstbuf = (mh == 0) ? g_aout : g_aout2;
    #pragma unroll
    for (int i = 0; i < 4; i++) {
        if (i == 3 && rt >= 8) break;
        int n0 = nb*200 + rt + 64*i;
        *(float4*)&dstbuf[(size_t)(blN + n0)*DM + h*HDM + vg*4] = acc[i];
    }
}

// =====================================================================
// Kernel 5: epilogue per 8 tokens; sums split-m partials on load.
// FF1/FF2 packed f32x2. (R11-verified core)
// =====================================================================
__global__ __launch_bounds__(256) void k5_ffn(
    const float* __restrict__ x,
    const float* __restrict__ Wo,  const float* __restrict__ bo,
    const float* __restrict__ Wf1, const float* __restrict__ bf1,
    const float* __restrict__ Wf2, const float* __restrict__ bf2,
    const float* __restrict__ g1,  const float* __restrict__ be1,
    const float* __restrict__ g2,  const float* __restrict__ be2,
    float* __restrict__ outp)
{
    int t0 = blockIdx.x * 8;
    __shared__ __align__(16) float s_ao[8*128];    // attn out
    __shared__ __align__(16) float s_xt[8*64];     // xt -> residual1
    __shared__ __align__(16) float s_r1t[64*10];   // LN1 out transposed [c][t], stride 10
    __shared__ __align__(16) float s_h1[8*1024];   // FF hidden [t][ff]
    __shared__ __align__(16) float s_sc[2048];     // partials scratch
    int tid = threadIdx.x;

    for (int i4 = tid; i4 < 8*32; i4 += 256) {
        float4 a = *(const float4*)&g_aout [(size_t)t0*DM + i4*4];
        float4 b = *(const float4*)&g_aout2[(size_t)t0*DM + i4*4];
        *(float4*)&s_ao[i4*4] = make_float4(a.x + b.x, a.y + b.y, a.z + b.z, a.w + b.w);
    }
    for (int idx = tid; idx < 8*64; idx += 256) {
        int t = t0 + (idx >> 6), c = idx & 63;
        int b = t / (LT*NPT); int rem = t % (LT*NPT);
        int l = rem / NPT;    int n = rem % NPT;
        s_xt[idx] = x[((size_t)(b*CH + c)*NPT + n)*LT + l];
    }
    __syncthreads();

    // ---- Wo: y = ao @ Wo. unit=(t,cq) 128 units x 2 dd-halves ----
    {
        int unit = tid >> 1, half = tid & 1;
        int t = unit >> 4, cq = unit & 15;
        const float4* Wo4 = (const float4*)Wo;
        float4 acc = make_float4(0.f, 0.f, 0.f, 0.f);
        int d0 = half*64;
        #pragma unroll 8
        for (int dd = d0; dd < d0 + 64; dd++) {
            float a = s_ao[t*128 + dd];
            float4 w = Wo4[dd*16 + cq];
            acc.x += a*w.x; acc.y += a*w.y; acc.z += a*w.z; acc.w += a*w.w;
        }
        *(float4*)&s_sc[(half*128 + unit)*4] = acc;
    }
    __syncthreads();
    for (int o = tid; o < 8*64; o += 256) {
        int c = o & 63;
        s_xt[o] += bo[c] + s_sc[o] + s_sc[512 + o];
    }
    __syncthreads();

    // ---- LN1 (warp per token), store TRANSPOSED [c][t] ----
    {
        int w = tid >> 5, lane = tid & 31;
        float v0 = s_xt[w*64 + lane], v1 = s_xt[w*64 + 32 + lane];
        float sum = v0 + v1;
        #pragma unroll
        for (int o = 16; o; o >>= 1) sum += __shfl_xor_sync(0xffffffffu, sum, o);
        float mean = sum * (1.0f/64.0f);
        float d0 = v0 - mean, d1 = v1 - mean;
        float vs = d0*d0 + d1*d1;
        #pragma unroll
        for (int o = 16; o; o >>= 1) vs += __shfl_xor_sync(0xffffffffu, vs, o);
        float inv = rsqrtf(vs*(1.0f/64.0f) + EPS_LN);
        s_r1t[lane*10 + w]        = d0*inv*g1[lane]      + be1[lane];
        s_r1t[(lane + 32)*10 + w] = d1*inv*g1[lane + 32] + be1[lane + 32];
    }
    __syncthreads();

    // ---- FF1 (f32x2): thread owns 4 ff cols; 4 token-pairs packed ----
    {
        const float4* Wf14 = (const float4*)Wf1;
        float4 bb = *(const float4*)&bf1[tid*4];
        unsigned long long acc2[4][4];
        {
            unsigned long long b0 = pack2(bb.x, bb.x), b1 = pack2(bb.y, bb.y);
            unsigned long long b2 = pack2(bb.z, bb.z), b3 = pack2(bb.w, bb.w);
            #pragma unroll
            for (int p = 0; p < 4; p++) {
                acc2[p][0] = b0; acc2[p][1] = b1; acc2[p][2] = b2; acc2[p][3] = b3;
            }
        }
        #pragma unroll 2
        for (int c = 0; c < 64; c++) {
            float4 w = Wf14[c*256 + tid];
            unsigned long long w0 = pack2(w.x, w.x), w1 = pack2(w.y, w.y);
            unsigned long long w2 = pack2(w.z, w.z), w3 = pack2(w.w, w.w);
            unsigned long long rv[4];
            #pragma unroll
            for (int p = 0; p < 4; p++)
                rv[p] = *(const unsigned long long*)&s_r1t[c*10 + 2*p];
            #pragma unroll
            for (int p = 0; p < 4; p++) {
                acc2[p][0] = fma2(rv[p], w0, acc2[p][0]);
                acc2[p][1] = fma2(rv[p], w1, acc2[p][1]);
                acc2[p][2] = fma2(rv[p], w2, acc2[p][2]);
                acc2[p][3] = fma2(rv[p], w3, acc2[p][3]);
            }
        }
        // relu + store to s_h1 [t][1024]
        #pragma unroll
        for (int p = 0; p < 4; p++) {
            float h0[4], h1[4];
            #pragma unroll
            for (int j = 0; j < 4; j++) {
                float a, bq; unpack2(acc2[p][j], a, bq);
                h0[j] = fmaxf(a, 0.f); h1[j] = fmaxf(bq, 0.f);
            }
            *(float4*)&s_h1[(2*p)*1024 + tid*4]     = make_float4(h0[0],h0[1],h0[2],h0[3]);
            *(float4*)&s_h1[(2*p + 1)*1024 + tid*4] = make_float4(h1[0],h1[1],h1[2],h1[3]);
        }
    }
    __syncthreads();

    // ---- FF2 (f32x2): 4 ff-groups x (16 c-quads x 4 token-pairs) ----
    {
        int grp = tid >> 6, rem = tid & 63;
        int cq  = rem & 15;            // c quad
        int tp  = rem >> 4;            // token pair
        const ulonglong2* Wf2v = (const ulonglong2*)Wf2;
        unsigned long long zA = pack2(0.f, 0.f);
        unsigned long long aA0 = zA, aA1 = zA, aB0 = zA, aB1 = zA;
        int f0 = grp*256;
        #pragma unroll 4
        for (int ff = f0; ff < f0 + 256; ff++) {
            ulonglong2 w2 = Wf2v[ff*16 + cq];     // (w0,w1),(w2,w3) packed
            float hA = s_h1[(2*tp)*1024 + ff];
            float hB = s_h1[(2*tp + 1)*1024 + ff];
            unsigned long long hA2 = pack2(hA, hA), hB2 = pack2(hB, hB);
            aA0 = fma2(hA2, w2.x, aA0);
            aA1 = fma2(hA2, w2.y, aA1);
            aB0 = fma2(hB2, w2.x, aB0);
            aB1 = fma2(hB2, w2.y, aB1);
        }
        __syncthreads();   // s_sc free (Wo partials consumed)
        float q0,q1,q2,q3;
        unpack2(aA0,q0,q1); unpack2(aA1,q2,q3);
        *(float4*)&s_sc[(grp*128 + (2*tp    )*16 + cq)*4] = make_float4(q0,q1,q2,q3);
        unpack2(aB0,q0,q1); unpack2(aB1,q2,q3);
        *(float4*)&s_sc[(grp*128 + (2*tp + 1)*16 + cq)*4] = make_float4(q0,q1,q2,q3);
    }
    __syncthreads();

    // ---- reduce FF2 partials + bias + residual (into s_r1t) ----
    for (int o = tid; o < 8*64; o += 256) {
        int t = o >> 6, c = o & 63;
        float y2 = bf2[c] + s_sc[o] + s_sc[512 + o] + s_sc[1024 + o] + s_sc[1536 + o];
        s_r1t[c*10 + t] += y2;
    }
    __syncthreads();

    // ---- LN2 + transposed store ----
    {
        int w = tid >> 5, lane = tid & 31;
        float v0 = s_r1t[lane*10 + w], v1 = s_r1t[(lane + 32)*10 + w];
        float sum = v0 + v1;
        #pragma unroll
        for (int o = 16; o; o >>= 1) sum += __shfl_xor_sync(0xffffffffu, sum, o);
        float mean = sum * (1.0f/64.0f);
        float d0 = v0 - mean, d1 = v1 - mean;
        float vs = d0*d0 + d1*d1;
        #pragma unroll
        for (int o = 16; o; o >>= 1) vs += __shfl_xor_sync(0xffffffffu, vs, o);
        float inv = rsqrtf(vs*(1.0f/64.0f) + EPS_LN);
        float o0 = d0*inv*g2[lane]      + be2[lane];
        float o1 = d1*inv*g2[lane + 32] + be2[lane + 32];

        int t = t0 + w;
        int b = t / (LT*NPT); int rem = t % (LT*NPT);
        int l = rem / NPT;    int n = rem % NPT;
        outp[((size_t)(b*CH + lane     )*NPT + n)*LT + l] = o0;
        outp[((size_t)(b*CH + lane + 32)*NPT + n)*LT + l] = o1;
    }
}

// =====================================================================
extern "C" void kernel_launch(void* const* d_in, const int* in_sizes, int n_in,
                              void* d_out, int out_size)
{
    const float* x    = (const float*)d_in[0];
    const float* xa1  = (const float*)d_in[1];
    const float* xa2  = (const float*)d_in[2];
    const float* WQ1  = (const float*)d_in[3];  const float* bQ1 = (const float*)d_in[4];
    const float* WQ2  = (const float*)d_in[5];  const float* bQ2 = (const float*)d_in[6];
    const float* WK1  = (const float*)d_in[7];  const float* bK1 = (const float*)d_in[8];
    const float* WK2  = (const float*)d_in[9];  const float* bK2 = (const float*)d_in[10];
    const float* WV   = (const float*)d_in[11]; const float* bV  = (const float*)d_in[12];
    const float* Wo   = (const float*)d_in[13]; const float* bo  = (const float*)d_in[14];
    const float* Wf1  = (const float*)d_in[15]; const float* bf1 = (const float*)d_in[16];
    const float* Wf2  = (const float*)d_in[17]; const float* bf2 = (const float*)d_in[18];
    const float* g1   = (const float*)d_in[19]; const float* be1 = (const float*)d_in[20];
    const float* g2   = (const float*)d_in[21]; const float* be2 = (const float*)d_in[22];
    const float* temp = (const float*)d_in[23];
    const float* alph = (const float*)d_in[24];

    float* outp = (float*)d_out;
    float* attn = outp + OUT0;                               // attn_flat region
    float* p2   = outp + OUT0 + (size_t)NROW*NPT;            // p2_flat region

    k1_proj<<<NTOK/4, 160>>>(x, xa1, xa2, WQ1, bQ1, WQ2, bQ2,
                             WK1, bK1, WK2, bK2, WV, bV);

    dim3 g2d(49, BSZ*NH*LT);
    k2_attn<<<g2d, 256>>>(attn, temp);

    k3_topk<<<NROW/8, 256>>>(attn, p2, alph);

    dim3 g4(4, BSZ*NH*LT);
    k4_av<<<g4, 256>>>();

    k5_ffn<<<NTOK/8, 256>>>(x, Wo, bo, Wf1, bf1, Wf2, bf2,
                            g1, be1, g2, be2, outp);
}

// round 17
// speedup vs baseline: 1.0233x; 1.0233x over previous
#include <cuda_runtime.h>
#include <cuda_bf16.h>
#include <math.h>
#include <stdint.h>

// ---------------- problem constants ----------------
#define BSZ 2
#define CH  64
#define NPT 400
#define LT  12
#define DM  128
#define NH  8
#define HDM 16
#define FFD 1024

#define NTOK (BSZ*LT*NPT)          // 9600 tokens (b,l,n)
#define NROW (BSZ*NH*LT*NPT)       // 76800 attention rows (b,h,l,n)
#define OUT0 (BSZ*CH*NPT*LT)       // 614400

#define EPS_LN 1e-5f
#define NEG_INF (__int_as_float(0xff800000))

// ---------------- f32x2 packed helpers ----------------
__device__ __forceinline__ unsigned long long fma2(
    unsigned long long a, unsigned long long b, unsigned long long c) {
    unsigned long long d;
    asm("fma.rn.f32x2 %0, %1, %2, %3;" : "=l"(d) : "l"(a), "l"(b), "l"(c));
    return d;
}
__device__ __forceinline__ unsigned long long pack2(float lo, float hi) {
    unsigned long long d;
    asm("mov.b64 %0, {%1, %2};" : "=l"(d) : "f"(lo), "f"(hi));
    return d;
}
__device__ __forceinline__ void unpack2(unsigned long long v, float& lo, float& hi) {
    asm("mov.b64 {%0, %1}, %2;" : "=f"(lo), "=f"(hi) : "l"(v));
}

// ---------------- scratch (device globals, no allocation) ----------------
__device__ float g_q1[NTOK*DM];
__device__ float g_q2[NTOK*DM];
__device__ float g_k1[NTOK*DM];
__device__ float g_k2[NTOK*DM];
__device__ float g_v [NTOK*DM];
__device__ float g_aout[NTOK*DM];
__device__ __nv_bfloat16 g_wb[(size_t)NROW*NPT];   // combined weights, bf16 (61MB)

// =====================================================================
// Kernel 1: projections + per-head l2 norm. 4 tokens per block,
// token-pairs packed f32x2; weight LDG amortized 4x.  (R12-verified)
// =====================================================================
__global__ __launch_bounds__(160) void k1_proj(
    const float* __restrict__ x, const float* __restrict__ xa1, const float* __restrict__ xa2,
    const float* __restrict__ WQ1, const float* __restrict__ bQ1,
    const float* __restrict__ WQ2, const float* __restrict__ bQ2,
    const float* __restrict__ WK1, const float* __restrict__ bK1,
    const float* __restrict__ WK2, const float* __restrict__ bK2,
    const float* __restrict__ WV,  const float* __restrict__ bV)
{
    int t0 = blockIdx.x * 4;
    __shared__ __align__(16) float s_in[3*CH*4];   // [arr*64+c][t], stride 4
    int tid = threadIdx.x;
    for (int idx = tid; idx < 3*CH*4; idx += 160) {
        int ci = idx >> 2, t = idx & 3;
        int arr = ci >> 6, c = ci & 63;
        const float* src = (arr == 0) ? x : (arr == 1 ? xa1 : xa2);
        int tt = t0 + t;
        int b = tt / (LT*NPT); int rem = tt % (LT*NPT);
        int l = rem / NPT;     int n = rem % NPT;
        s_in[ci*4 + t] = src[((size_t)(b*CH + c)*NPT + n)*LT + l];
    }
    __syncthreads();

    int p = tid >> 5, dg = tid & 31;       // p uniform per warp
    const float* W    = (p==0)?WQ1 : (p==1)?WQ2 : (p==2)?WK1 : (p==3)?WK2 : WV;
    const float* bias = (p==0)?bQ1 : (p==1)?bQ2 : (p==2)?bK1 : (p==3)?bK2 : bV;
    int soff = (p==0) ? CH : (p==1 ? 2*CH : 0);   // xa1 / xa2 / x

    float4 bb = *(const float4*)&bias[4*dg];
    unsigned long long acc2[2][4];
    {
        unsigned long long b0 = pack2(bb.x, bb.x), b1 = pack2(bb.y, bb.y);
        unsigned long long b2 = pack2(bb.z, bb.z), b3 = pack2(bb.w, bb.w);
        acc2[0][0] = b0; acc2[0][1] = b1; acc2[0][2] = b2; acc2[0][3] = b3;
        acc2[1][0] = b0; acc2[1][1] = b1; acc2[1][2] = b2; acc2[1][3] = b3;
    }
    #pragma unroll 4
    for (int c = 0; c < CH; c++) {
        float4 w = *(const float4*)&W[c*DM + 4*dg];
        unsigned long long w0 = pack2(w.x, w.x), w1 = pack2(w.y, w.y);
        unsigned long long w2 = pack2(w.z, w.z), w3 = pack2(w.w, w.w);
        unsigned long long rv0 = *(const unsigned long long*)&s_in[(soff + c)*4];
        unsigned long long rv1 = *(const unsigned long long*)&s_in[(soff + c)*4 + 2];
        acc2[0][0] = fma2(rv0, w0, acc2[0][0]);
        acc2[0][1] = fma2(rv0, w1, acc2[0][1]);
        acc2[0][2] = fma2(rv0, w2, acc2[0][2]);
        acc2[0][3] = fma2(rv0, w3, acc2[0][3]);
        acc2[1][0] = fma2(rv1, w0, acc2[1][0]);
        acc2[1][1] = fma2(rv1, w1, acc2[1][1]);
        acc2[1][2] = fma2(rv1, w2, acc2[1][2]);
        acc2[1][3] = fma2(rv1, w3, acc2[1][3]);
    }
    // unpack to per-token values v[t][j]
    float v[4][4];
    #pragma unroll
    for (int pp = 0; pp < 2; pp++)
        #pragma unroll
        for (int j = 0; j < 4; j++)
            unpack2(acc2[pp][j], v[2*pp][j], v[2*pp + 1][j]);

    float* dst = (p==0)?g_q1 : (p==1)?g_q2 : (p==2)?g_k1 : (p==3)?g_k2 : g_v;
    #pragma unroll
    for (int t = 0; t < 4; t++) {
        float a0 = v[t][0], a1 = v[t][1], a2 = v[t][2], a3 = v[t][3];
        if (p < 4) {  // l2norm per head (head = 16 dims = 4 consecutive lanes)
            float ss = a0*a0 + a1*a1 + a2*a2 + a3*a3;
            ss += __shfl_xor_sync(0xffffffffu, ss, 1);
            ss += __shfl_xor_sync(0xffffffffu, ss, 2);
            float inv = 1.0f / fmaxf(sqrtf(ss), 1e-12f);
            a0 *= inv; a1 *= inv; a2 *= inv; a3 *= inv;
        }
        *(float4*)&dst[(size_t)(t0 + t)*DM + 4*dg] = make_float4(a0, a1, a2, a3);
    }
}

// =====================================================================
// Kernel 2: attn = temp*(q1.k1 + q2.k2) via f32x2 packed pairs.
// STRIDED m-assignment: conflict-free LDS.64.  (R13-verified)
// =====================================================================
__global__ __launch_bounds__(256) void k2_attn(
    float* __restrict__ attn, const float* __restrict__ temperature)
{
    int tile = blockIdx.x;
    int nb = tile / 7, mb = tile % 7;
    int bhl = blockIdx.y;
    int b = bhl / (NH*LT); int h = (bhl / LT) % NH; int l = bhl % LT;
    int baset = (b*LT + l)*NPT;

    __shared__ __align__(16) unsigned long long Qs2[64*17];  // [n][d] pairs
    __shared__ __align__(16) unsigned long long Ks2[64*17];  // [m][d] pairs
    int tid = threadIdx.x;

    {
        int row = tid >> 2, qq = tid & 3;
        int n = nb*64 + row;
        float4 a = make_float4(0,0,0,0), bq = a;
        if (n < NPT) {
            size_t base = (size_t)(baset + n)*DM + h*HDM;
            a  = *(const float4*)&g_q1[base + qq*4];
            bq = *(const float4*)&g_q2[base + qq*4];
        }
        unsigned long long* dstq = &Qs2[row*17 + qq*4];
        dstq[0] = pack2(a.x, bq.x); dstq[1] = pack2(a.y, bq.y);
        dstq[2] = pack2(a.z, bq.z); dstq[3] = pack2(a.w, bq.w);
        int m = mb*64 + row;
        a = make_float4(0,0,0,0); bq = a;
        if (m < NPT) {
            size_t base = (size_t)(baset + m)*DM + h*HDM;
            a  = *(const float4*)&g_k1[base + qq*4];
            bq = *(const float4*)&g_k2[base + qq*4];
        }
        unsigned long long* dstk = &Ks2[row*17 + qq*4];
        dstk[0] = pack2(a.x, bq.x); dstk[1] = pack2(a.y, bq.y);
        dstk[2] = pack2(a.z, bq.z); dstk[3] = pack2(a.w, bq.w);
    }
    __syncthreads();

    int tx = tid & 15, ty = tid >> 4;     // n = ty + 16i, m = tx + 16j
    unsigned long long acc2[4][4];
    {
        unsigned long long z = pack2(0.f, 0.f);
        #pragma unroll
        for (int i = 0; i < 4; i++)
            #pragma unroll
            for (int j = 0; j < 4; j++) acc2[i][j] = z;
    }
    #pragma unroll
    for (int kk = 0; kk < 16; kk++) {
        unsigned long long qr[4], kr[4];
        #pragma unroll
        for (int i = 0; i < 4; i++) qr[i] = Qs2[(ty + 16*i)*17 + kk];
        #pragma unroll
        for (int j = 0; j < 4; j++) kr[j] = Ks2[(tx + 16*j)*17 + kk];
        #pragma unroll
        for (int i = 0; i < 4; i++)
            #pragma unroll
            for (int j = 0; j < 4; j++)
                acc2[i][j] = fma2(qr[i], kr[j], acc2[i][j]);
    }

    float temp = temperature[h];
    size_t base = (size_t)bhl * NPT * NPT;
    #pragma unroll
    for (int i = 0; i < 4; i++) {
        int n = nb*64 + ty + 16*i;
        if (n >= NPT) continue;
        #pragma unroll
        for (int j = 0; j < 4; j++) {
            int m = mb*64 + tx + 16*j;
            if (m < NPT) {
                float lo, hi; unpack2(acc2[i][j], lo, hi);
                attn[base + (size_t)n*NPT + m] = (lo + hi)*temp;
            }
        }
    }
}

// =====================================================================
// Kernel 3: warp-per-row EXACT select (1 shared histogram, plain
// atomics), softmax, writes p2_flat (fp32) + g_wb (bf16).
// =====================================================================
__device__ __forceinline__ void walk_bins(
    const unsigned int c[8], unsigned int k, int lane,
    unsigned int& bsel, unsigned int& krem)
{
    unsigned int lsum = 0;
    #pragma unroll
    for (int b = 0; b < 8; b++) lsum += c[b];
    unsigned int s = lsum;                       // suffix sum over lanes >= lane
    #pragma unroll
    for (int o = 1; o < 32; o <<= 1) {
        unsigned int t = __shfl_down_sync(0xffffffffu, s, o);
        if (lane + o < 32) s += t;
    }
    unsigned int excl = __shfl_down_sync(0xffffffffu, s, 1);
    if (lane == 31) excl = 0u;
    unsigned int ball = __ballot_sync(0xffffffffu, (excl < k) && (excl + lsum >= k));
    int src = __ffs((int)ball) - 1;
    unsigned int dig = 0, nk = 0;
    if (lane == src) {
        unsigned int cum = excl, cumsel = excl;
        int bs = 0; bool fnd = false;
        #pragma unroll
        for (int b = 7; b >= 0; b--) {
            if (!fnd && (cum + c[b] >= k)) { bs = b; cumsel = cum; fnd = true; }
            if (!fnd) cum += c[b];
        }
        dig = (unsigned)(lane*8 + bs);
        nk  = k - cumsel;
    }
    bsel = __shfl_sync(0xffffffffu, dig, src);
    krem = __shfl_sync(0xffffffffu, nk,  src);
}

__device__ __forceinline__ unsigned int select_kth(
    const unsigned int u[13], int lane, unsigned int* hist,
    unsigned int lo, int shift, const unsigned int c0[8], unsigned int k)
{
    unsigned int bsel, krem;
    walk_bins(c0, k, lane, bsel, krem);
    lo += bsel << shift;
    k = krem;
    while (shift > 0) {                      // warp-uniform
        int ns = (shift > 8) ? shift - 8 : 0;
        unsigned int hi2 = lo + ((1u << shift) - 1u);
        #pragma unroll
        for (int b = 0; b < 8; b++) hist[lane*8 + b] = 0u;
        __syncwarp();
        #pragma unroll
        for (int i = 0; i < 13; i++) {
            unsigned int key = u[i];
            if (key >= lo && key <= hi2)
                atomicAdd(&hist[(key - lo) >> ns], 1u);
        }
        __syncwarp();
        unsigned int c[8];
        #pragma unroll
        for (int b = 0; b < 8; b++) c[b] = hist[lane*8 + b];
        __syncwarp();
        walk_bins(c, k, lane, bsel, krem);
        lo += bsel << ns;
        k = krem;
        shift = ns;
    }
    return lo;   // exact key of k-th largest
}

__global__ __launch_bounds__(256) void k3_topk(
    const float* __restrict__ attn, float* __restrict__ p2out,
    const float* __restrict__ alphas)
{
    __shared__ unsigned int hist_all[8*256];
    int wib = threadIdx.x >> 5, lane = threadIdx.x & 31;
    unsigned int* hist = &hist_all[wib*256];
    int r = blockIdx.x*8 + wib;

    const float* row = attn + (size_t)r*NPT;
    float f[13]; unsigned int u[13];
    #pragma unroll
    for (int i = 0; i < 13; i++) {
        int m = lane + 32*i;
        float v = (m < NPT) ? row[m] : NEG_INF;
        f[i] = v;
        unsigned int bb = __float_as_uint(v);
        unsigned int key = (bb & 0x80000000u) ? ~bb : (bb | 0x80000000u);
        u[i] = (m < NPT) ? key : 0u;        // pads: key 0, excluded everywhere
    }
    float mx = NEG_INF;
    unsigned int lo = 0xFFFFFFFFu, hi = 0u;
    #pragma unroll
    for (int i = 0; i < 13; i++) {
        int m = lane + 32*i;
        if (m < NPT) {
            mx = fmaxf(mx, f[i]);
            lo = min(lo, u[i]);
            hi = max(hi, u[i]);
        }
    }
    #pragma unroll
    for (int o = 16; o; o >>= 1) {
        mx = fmaxf(mx, __shfl_xor_sync(0xffffffffu, mx, o));
        lo = min(lo, __shfl_xor_sync(0xffffffffu, lo, o));
        hi = max(hi, __shfl_xor_sync(0xffffffffu, hi, o));
    }
    unsigned int range = hi - lo;
    int rb = (range == 0u) ? 0 : (32 - __clz(range));
    int shift = (rb > 8) ? rb - 8 : 0;

    // single full histogram pass (plain atomics; shared by both selects)
    #pragma unroll
    for (int bq = 0; bq < 8; bq++) hist[lane*8 + bq] = 0u;
    __syncwarp();
    #pragma unroll
    for (int i = 0; i < 13; i++) {
        int m = lane + 32*i;
        if (m < NPT) atomicAdd(&hist[(u[i] - lo) >> shift], 1u);
    }
    __syncwarp();
    unsigned int c0[8];
    #pragma unroll
    for (int bq = 0; bq < 8; bq++) c0[bq] = hist[lane*8 + bq];
    __syncwarp();

    unsigned int t1u = select_kth(u, lane, hist, lo, shift, c0, 200u);
    unsigned int t2u = select_kth(u, lane, hist, lo, shift, c0, 100u);

    float l1 = 0.f, l2 = 0.f;
    #pragma unroll
    for (int i = 0; i < 13; i++) {
        float e = __expf(f[i] - mx);        // pads: exp(-inf)=0
        f[i] = e;
        if (u[i] >= t1u) { l1 += e; if (u[i] >= t2u) l2 += e; }
    }
    #pragma unroll
    for (int o = 16; o; o >>= 1) {
        l1 += __shfl_xor_sync(0xffffffffu, l1, o);
        l2 += __shfl_xor_sync(0xffffffffu, l2, o);
    }
    float i1 = 1.0f/l1, i2 = 1.0f/l2;

    float a0 = alphas[0], a1 = alphas[1];
    float am = fmaxf(a0, a1);
    float e0 = __expf(a0 - am), e1 = __expf(a1 - am);
    float al0 = e0/(e0 + e1), al1 = e1/(e0 + e1);

    float* prow = p2out + (size_t)r*NPT;
    __nv_bfloat16* wrow = g_wb + (size_t)r*NPT;
    #pragma unroll
    for (int i = 0; i < 13; i++) {
        int m = lane + 32*i;
        if (m < NPT) {
            float e  = f[i];
            float p1 = (u[i] >= t1u) ? e*i1 : 0.f;
            float p2 = (u[i] >= t2u) ? e*i2 : 0.f;
            prow[m] = p2;
            wrow[m] = __float2bfloat16(al0*p1 + al1*p2);
        }
    }
}

// =====================================================================
// Kernel 4: aout = W @ V per (b,h,l). 200-row blocks, 4 rows/thread,
// 40-col m-chunks, stride-44 smem. W read as bf16, converted to fp32
// during staging (halved LDG bytes + count). (R14 tiling, R15 grid)
// =====================================================================
__global__ __launch_bounds__(256) void k4_av()
{
    int nb  = blockIdx.x;            // 0..1, 200 rows each
    int bhl = blockIdx.y;
    int b = bhl / (NH*LT); int h = (bhl / LT) % NH; int l = bhl % LT;
    int blN = (b*LT + l)*NPT;

    __shared__ __align__(16) float Wsh[200*44];   // 35.2KB
    __shared__ __align__(16) float Vsh[40*16];    // 2.56KB

    int tid = threadIdx.x;
    int vg = tid & 3, rt = tid >> 2;              // rt 0..63

    size_t wbase = ((size_t)bhl*NPT + nb*200)*NPT;

    float4 acc[4];
    #pragma unroll
    for (int i = 0; i < 4; i++) acc[i] = make_float4(0.f, 0.f, 0.f, 0.f);

    for (int mc = 0; mc < NPT; mc += 40) {
        __syncthreads();
        // stage W: 200 rows x 40 bf16 = 200 x 5 uint4 (8 bf16 each)
        for (int idx = tid; idx < 200*5; idx += 256) {
            int rr = idx/5, cc = idx%5;
            const uint4* src = (const uint4*)&g_wb[wbase + (size_t)rr*NPT + mc + cc*8];
            uint4 pk = *src;
            const __nv_bfloat162* h2 = (const __nv_bfloat162*)&pk;
            float2 f0 = __bfloat1622float2(h2[0]);
            float2 f1 = __bfloat1622float2(h2[1]);
            float2 f2 = __bfloat1622float2(h2[2]);
            float2 f3 = __bfloat1622float2(h2[3]);
            float* dst = &Wsh[rr*44 + cc*8];
            *(float4*)&dst[0] = make_float4(f0.x, f0.y, f1.x, f1.y);
            *(float4*)&dst[4] = make_float4(f2.x, f2.y, f3.x, f3.y);
        }
        for (int idx = tid; idx < 40*4; idx += 256) {
            int rr = idx >> 2, c4 = idx & 3;
            *(float4*)&Vsh[rr*16 + c4*4] =
                *(const float4*)&g_v[(size_t)(blN + mc + rr)*DM + h*HDM + c4*4];
        }
        __syncthreads();
        #pragma unroll 2
        for (int ml = 0; ml < 40; ml += 4) {
            float4 v0 = *(const float4*)&Vsh[(ml+0)*16 + vg*4];
            float4 v1 = *(const float4*)&Vsh[(ml+1)*16 + vg*4];
            float4 v2 = *(const float4*)&Vsh[(ml+2)*16 + vg*4];
            float4 v3 = *(const float4*)&Vsh[(ml+3)*16 + vg*4];
            #pragma unroll
            for (int i = 0; i < 4; i++) {
                if (i == 3 && rt >= 8) break;        // rows 192..199 only
                float4 w = *(const float4*)&Wsh[(rt + 64*i)*44 + ml];
                acc[i].x += w.x*v0.x + w.y*v1.x + w.z*v2.x + w.w*v3.x;
                acc[i].y += w.x*v0.y + w.y*v1.y + w.z*v2.y + w.w*v3.y;
                acc[i].z += w.x*v0.z + w.y*v1.z + w.z*v2.z + w.w*v3.z;
                acc[i].w += w.x*v0.w + w.y*v1.w + w.z*v2.w + w.w*v3.w;
            }
        }
    }
    #pragma unroll
    for (int i = 0; i < 4; i++) {
        if (i == 3 && rt >= 8) break;
        int n0 = nb*200 + rt + 64*i;
        *(float4*)&g_aout[(size_t)(blN + n0)*DM + h*HDM + vg*4] = acc[i];
    }
}

// =====================================================================
// Kernel 5: epilogue per 8 tokens; FF1/FF2 packed f32x2. (R11/R15-verified)
// =====================================================================
__global__ __launch_bounds__(256) void k5_ffn(
    const float* __restrict__ x,
    const float* __restrict__ Wo,  const float* __restrict__ bo,
    const float* __restrict__ Wf1, const float* __restrict__ bf1,
    const float* __restrict__ Wf2, const float* __restrict__ bf2,
    const float* __restrict__ g1,  const float* __restrict__ be1,
    const float* __restrict__ g2,  const float* __restrict__ be2,
    float* __restrict__ outp)
{
    int t0 = blockIdx.x * 8;
    __shared__ __align__(16) float s_ao[8*128];    // attn out
    __shared__ __align__(16) float s_xt[8*64];     // xt -> residual1
    __shared__ __align__(16) float s_r1t[64*10];   // LN1 out transposed [c][t], stride 10
    __shared__ __align__(16) float s_h1[8*1024];   // FF hidden [t][ff]
    __shared__ __align__(16) float s_sc[2048];     // partials scratch
    int tid = threadIdx.x;

    for (int i4 = tid; i4 < 8*32; i4 += 256)
        *(float4*)&s_ao[i4*4] = *(const float4*)&g_aout[(size_t)t0*DM + i4*4];
    for (int idx = tid; idx < 8*64; idx += 256) {
        int t = t0 + (idx >> 6), c = idx & 63;
        int b = t / (LT*NPT); int rem = t % (LT*NPT);
        int l = rem / NPT;    int n = rem % NPT;
        s_xt[idx] = x[((size_t)(b*CH + c)*NPT + n)*LT + l];
    }
    __syncthreads();

    // ---- Wo: y = ao @ Wo. unit=(t,cq) 128 units x 2 dd-halves ----
    {
        int unit = tid >> 1, half = tid & 1;
        int t = unit >> 4, cq = unit & 15;
        const float4* Wo4 = (const float4*)Wo;
        float4 acc = make_float4(0.f, 0.f, 0.f, 0.f);
        int d0 = half*64;
        #pragma unroll 8
        for (int dd = d0; dd < d0 + 64; dd++) {
            float a = s_ao[t*128 + dd];
            float4 w = Wo4[dd*16 + cq];
            acc.x += a*w.x; acc.y += a*w.y; acc.z += a*w.z; acc.w += a*w.w;
        }
        *(float4*)&s_sc[(half*128 + unit)*4] = acc;
    }
    __syncthreads();
    for (int o = tid; o < 8*64; o += 256) {
        int c = o & 63;
        s_xt[o] += bo[c] + s_sc[o] + s_sc[512 + o];
    }
    __syncthreads();

    // ---- LN1 (warp per token), store TRANSPOSED [c][t] ----
    {
        int w = tid >> 5, lane = tid & 31;
        float v0 = s_xt[w*64 + lane], v1 = s_xt[w*64 + 32 + lane];
        float sum = v0 + v1;
        #pragma unroll
        for (int o = 16; o; o >>= 1) sum += __shfl_xor_sync(0xffffffffu, sum, o);
        float mean = sum * (1.0f/64.0f);
        float d0 = v0 - mean, d1 = v1 - mean;
        float vs = d0*d0 + d1*d1;
        #pragma unroll
        for (int o = 16; o; o >>= 1) vs += __shfl_xor_sync(0xffffffffu, vs, o);
        float inv = rsqrtf(vs*(1.0f/64.0f) + EPS_LN);
        s_r1t[lane*10 + w]        = d0*inv*g1[lane]      + be1[lane];
        s_r1t[(lane + 32)*10 + w] = d1*inv*g1[lane + 32] + be1[lane + 32];
    }
    __syncthreads();

    // ---- FF1 (f32x2): thread owns 4 ff cols; 4 token-pairs packed ----
    {
        const float4* Wf14 = (const float4*)Wf1;
        float4 bb = *(const float4*)&bf1[tid*4];
        unsigned long long acc2[4][4];
        {
            unsigned long long b0 = pack2(bb.x, bb.x), b1 = pack2(bb.y, bb.y);
            unsigned long long b2 = pack2(bb.z, bb.z), b3 = pack2(bb.w, bb.w);
            #pragma unroll
            for (int p = 0; p < 4; p++) {
                acc2[p][0] = b0; acc2[p][1] = b1; acc2[p][2] = b2; acc2[p][3] = b3;
            }
        }
        #pragma unroll 2
        for (int c = 0; c < 64; c++) {
            float4 w = Wf14[c*256 + tid];
            unsigned long long w0 = pack2(w.x, w.x), w1 = pack2(w.y, w.y);
            unsigned long long w2 = pack2(w.z, w.z), w3 = pack2(w.w, w.w);
            unsigned long long rv[4];
            #pragma unroll
            for (int p = 0; p < 4; p++)
                rv[p] = *(const unsigned long long*)&s_r1t[c*10 + 2*p];
            #pragma unroll
            for (int p = 0; p < 4; p++) {
                acc2[p][0] = fma2(rv[p], w0, acc2[p][0]);
                acc2[p][1] = fma2(rv[p], w1, acc2[p][1]);
                acc2[p][2] = fma2(rv[p], w2, acc2[p][2]);
                acc2[p][3] = fma2(rv[p], w3, acc2[p][3]);
            }
        }
        // relu + store to s_h1 [t][1024]
        #pragma unroll
        for (int p = 0; p < 4; p++) {
            float h0[4], h1[4];
            #pragma unroll
            for (int j = 0; j < 4; j++) {
                float a, bq; unpack2(acc2[p][j], a, bq);
                h0[j] = fmaxf(a, 0.f); h1[j] = fmaxf(bq, 0.f);
            }
            *(float4*)&s_h1[(2*p)*1024 + tid*4]     = make_float4(h0[0],h0[1],h0[2],h0[3]);
            *(float4*)&s_h1[(2*p + 1)*1024 + tid*4] = make_float4(h1[0],h1[1],h1[2],h1[3]);
        }
    }
    __syncthreads();

    // ---- FF2 (f32x2): 4 ff-groups x (16 c-quads x 4 token-pairs) ----
    {
        int grp = tid >> 6, rem = tid & 63;
        int cq  = rem & 15;            // c quad
        int tp  = rem >> 4;            // token pair
        const ulonglong2* Wf2v = (const ulonglong2*)Wf2;
        unsigned long long zA = pack2(0.f, 0.f);
        unsigned long long aA0 = zA, aA1 = zA, aB0 = zA, aB1 = zA;
        int f0 = grp*256;
        #pragma unroll 4
        for (int ff = f0; ff < f0 + 256; ff++) {
            ulonglong2 w2 = Wf2v[ff*16 + cq];     // (w0,w1),(w2,w3) packed
            float hA = s_h1[(2*tp)*1024 + ff];
            float hB = s_h1[(2*tp + 1)*1024 + ff];
            unsigned long long hA2 = pack2(hA, hA), hB2 = pack2(hB, hB);
            aA0 = fma2(hA2, w2.x, aA0);
            aA1 = fma2(hA2, w2.y, aA1);
            aB0 = fma2(hB2, w2.x, aB0);
            aB1 = fma2(hB2, w2.y, aB1);
        }
        __syncthreads();   // s_sc free (Wo partials consumed)
        float q0,q1,q2,q3;
        unpack2(aA0,q0,q1); unpack2(aA1,q2,q3);
        *(float4*)&s_sc[(grp*128 + (2*tp    )*16 + cq)*4] = make_float4(q0,q1,q2,q3);
        unpack2(aB0,q0,q1); unpack2(aB1,q2,q3);
        *(float4*)&s_sc[(grp*128 + (2*tp + 1)*16 + cq)*4] = make_float4(q0,q1,q2,q3);
    }
    __syncthreads();

    // ---- reduce FF2 partials + bias + residual (into s_r1t) ----
    for (int o = tid; o < 8*64; o += 256) {
        int t = o >> 6, c = o & 63;
        float y2 = bf2[c] + s_sc[o] + s_sc[512 + o] + s_sc[1024 + o] + s_sc[1536 + o];
        s_r1t[c*10 + t] += y2;
    }
    __syncthreads();

    // ---- LN2 + transposed store ----
    {
        int w = tid >> 5, lane = tid & 31;
        float v0 = s_r1t[lane*10 + w], v1 = s_r1t[(lane + 32)*10 + w];
        float sum = v0 + v1;
        #pragma unroll
        for (int o = 16; o; o >>= 1) sum += __shfl_xor_sync(0xffffffffu, sum, o);
        float mean = sum * (1.0f/64.0f);
        float d0 = v0 - mean, d1 = v1 - mean;
        float vs = d0*d0 + d1*d1;
        #pragma unroll
        for (int o = 16; o; o >>= 1) vs += __shfl_xor_sync(0xffffffffu, vs, o);
        float inv = rsqrtf(vs*(1.0f/64.0f) + EPS_LN);
        float o0 = d0*inv*g2[lane]      + be2[lane];
        float o1 = d1*inv*g2[lane + 32] + be2[lane + 32];

        int t = t0 + w;
        int b = t / (LT*NPT); int rem = t % (LT*NPT);
        int l = rem / NPT;    int n = rem % NPT;
        outp[((size_t)(b*CH + lane     )*NPT + n)*LT + l] = o0;
        outp[((size_t)(b*CH + lane + 32)*NPT + n)*LT + l] = o1;
    }
}

// =====================================================================
extern "C" void kernel_launch(void* const* d_in, const int* in_sizes, int n_in,
                              void* d_out, int out_size)
{
    const float* x    = (const float*)d_in[0];
    const float* xa1  = (const float*)d_in[1];
    const float* xa2  = (const float*)d_in[2];
    const float* WQ1  = (const float*)d_in[3];  const float* bQ1 = (const float*)d_in[4];
    const float* WQ2  = (const float*)d_in[5];  const float* bQ2 = (const float*)d_in[6];
    const float* WK1  = (const float*)d_in[7];  const float* bK1 = (const float*)d_in[8];
    const float* WK2  = (const float*)d_in[9];  const float* bK2 = (const float*)d_in[10];
    const float* WV   = (const float*)d_in[11]; const float* bV  = (const float*)d_in[12];
    const float* Wo   = (const float*)d_in[13]; const float* bo  = (const float*)d_in[14];
    const float* Wf1  = (const float*)d_in[15]; const float* bf1 = (const float*)d_in[16];
    const float* Wf2  = (const float*)d_in[17]; const float* bf2 = (const float*)d_in[18];
    const float* g1   = (const float*)d_in[19]; const float* be1 = (const float*)d_in[20];
    const float* g2   = (const float*)d_in[21]; const float* be2 = (const float*)d_in[22];
    const float* temp = (const float*)d_in[23];
    const float* alph = (const float*)d_in[24];

    float* outp = (float*)d_out;
    float* attn = outp + OUT0;                               // attn_flat region
    float* p2   = outp + OUT0 + (size_t)NROW*NPT;            // p2_flat region

    k1_proj<<<NTOK/4, 160>>>(x, xa1, xa2, WQ1, bQ1, WQ2, bQ2,
                             WK1, bK1, WK2, bK2, WV, bV);

    dim3 g2d(49, BSZ*NH*LT);
    k2_attn<<<g2d, 256>>>(attn, temp);

    k3_topk<<<NROW/8, 256>>>(attn, p2, alph);

    dim3 g4(2, BSZ*NH*LT);
    k4_av<<<g4, 256>>>();

    k5_ffn<<<NTOK/8, 256>>>(x, Wo, bo, Wf1, bf1, Wf2, bf2,
                            g1, be1, g2, be2, outp);
}